// round 17
// baseline (speedup 1.0000x reference)
#include <cuda_runtime.h>
#include <math.h>
#include <stdint.h>

// Problem constants
#define V 50000
#define E 300
#define H 2048
#define L 512
#define CAT (E + H)          // 2348
#define CAT4 587             // float4 per 2348-row
#define E4 75                // float4 in embedded part (300/4)
#define H4 512               // float4 per 2048-row
#define G3H (3 * H)          // 6144

// Launch geometry: 4 CTAs per SM on 148 SMs -> all blocks resident
#define NB 592
#define NT 256
#define NWARP ((NB * NT) / 32)   // 4736

// ---------------- device scratch (allocation-free) ----------------
__device__ float g_attn_logits[L];
__device__ __align__(16) float g_aa[H];       // attn_applied
__device__ __align__(16) float g_x[H];        // relu(comb) output
__device__ float g_gh[G3H];
__device__ float g_gi[G3H];
__device__ __align__(16) float g_hnew[H];
__device__ float g_logits[V];
__device__ float g_pm[NB];
__device__ float g_ps[NB];
__device__ unsigned int g_bar_a;              // monotone arrive counter
__device__ volatile unsigned int g_bar_v;     // monotone release value

// ---------------- fast grid-wide barrier (volatile-load spin) -------------
__device__ __forceinline__ void grid_bar() {
    __syncthreads();
    if (threadIdx.x == 0) {
        __threadfence();
        unsigned int t = atomicAdd(&g_bar_a, 1u) + 1u;
        unsigned int target = ((t + NB - 1u) / NB) * NB;
        if (t == target) {
            __threadfence();
            g_bar_v = target;                 // release
        } else {
            while (g_bar_v < target) { }      // volatile poll (L2)
        }
        __threadfence();
    }
    __syncthreads();
}

__device__ __forceinline__ float warp_sum(float a) {
#pragma unroll
    for (int o = 16; o; o >>= 1) a += __shfl_down_sync(0xffffffffu, a, o);
    return a;
}

__global__ void __launch_bounds__(NT, 4)
fused_decoder(const int* __restrict__ input,
              const float* __restrict__ hidden,
              const float* __restrict__ enc,
              const float* __restrict__ emb,
              const float4* __restrict__ attn_W4,
              const float* __restrict__ attn_b,
              const float4* __restrict__ comb_W4,
              const float* __restrict__ comb_b,
              const float4* __restrict__ Wih4,
              const float4* __restrict__ Whh4,
              const float* __restrict__ b_ih,
              const float* __restrict__ b_hh,
              const float4* __restrict__ outW4,
              const float* __restrict__ out_b,
              float* __restrict__ out_logp,
              float* __restrict__ out_h,
              float* __restrict__ out_attn) {
    __shared__ float s_w[L];                  // softmax weights (2KB)
    __shared__ float sA[8];
    __shared__ float sB[8];
    __shared__ float s_bcast;

    const int tid  = threadIdx.x;
    const int lane = tid & 31;
    const int wid  = tid >> 5;
    const int gt   = blockIdx.x * NT + tid;
    const int gw   = gt >> 5;
    const float4* h04     = (const float4*)hidden;
    const float4* embrow4 = (const float4*)(emb + (size_t)input[0] * E);

    // ---- S1: attn logits (512 x 2348, x = [emb|h0] read directly)
    //          + gh = W_hh @ h0 (6144 x 2048) ----
    for (int w = gw; w < L + G3H; w += NWARP) {
        float acc = 0.f;
        if (w < L) {
            const float4* Wr = attn_W4 + (size_t)w * CAT4;
#pragma unroll 4
            for (int k = 0; k < 19; ++k) {
                int idx = k * 32 + lane;
                if (idx < CAT4) {
                    const float4* xp = (idx < E4) ? (embrow4 + idx) : (h04 + (idx - E4));
                    float4 a = Wr[idx], b = *xp;
                    acc += a.x * b.x + a.y * b.y + a.z * b.z + a.w * b.w;
                }
            }
            acc = warp_sum(acc);
            if (lane == 0) g_attn_logits[w] = acc + attn_b[w];
        } else {
            int r = w - L;
            const float4* Wr = Whh4 + (size_t)r * H4;
#pragma unroll 8
            for (int k = 0; k < 16; ++k) {
                int idx = k * 32 + lane;
                float4 a = Wr[idx], b = h04[idx];
                acc += a.x * b.x + a.y * b.y + a.z * b.z + a.w * b.w;
            }
            acc = warp_sum(acc);
            if (lane == 0) g_gh[r] = acc + b_hh[r];
        }
    }
    grid_bar();  // B1

    // ---- S2: per-block redundant softmax (into smem) + attn_applied ----
    {
        float v0 = g_attn_logits[tid];
        float v1 = g_attn_logits[tid + 256];
        float m = fmaxf(v0, v1);
#pragma unroll
        for (int o = 16; o; o >>= 1) m = fmaxf(m, __shfl_xor_sync(0xffffffffu, m, o));
        if (lane == 0) sA[wid] = m;
        __syncthreads();
        if (wid == 0) {
            float mm = (lane < 8) ? sA[lane] : -INFINITY;
#pragma unroll
            for (int o = 4; o; o >>= 1) mm = fmaxf(mm, __shfl_xor_sync(0xffffffffu, mm, o));
            if (lane == 0) s_bcast = mm;
        }
        __syncthreads();
        float M = s_bcast;
        float p0 = expf(v0 - M), p1 = expf(v1 - M);
        float s = warp_sum(p0 + p1);
        if (lane == 0) sA[wid] = s;
        __syncthreads();
        if (wid == 0) {
            float ss = (lane < 8) ? sA[lane] : 0.f;
#pragma unroll
            for (int o = 4; o; o >>= 1) ss += __shfl_xor_sync(0xffffffffu, ss, o);
            if (lane == 0) s_bcast = ss;
        }
        __syncthreads();
        float inv = 1.f / s_bcast;
        float w0 = p0 * inv, w1 = p1 * inv;
        s_w[tid] = w0;       s_w[tid + 256] = w1;
        if (blockIdx.x == 0) { out_attn[tid] = w0; out_attn[tid + 256] = w1; }
        __syncthreads();

        // attn_applied: one warp per encoder column, lanes stride L
        if (gw < H) {
            int col = gw;
            float acc = 0.f;
#pragma unroll
            for (int it = 0; it < L / 32; ++it) {
                int l = it * 32 + lane;
                acc += s_w[l] * enc[(size_t)l * H + col];
            }
            acc = warp_sum(acc);
            if (lane == 0) g_aa[col] = acc;
        }
    }
    grid_bar();  // B2

    // ---- S3: combine + relu: 2048 rows x 2348, x = [emb|attn_applied] ----
    {
        const float4* aa4 = (const float4*)g_aa;
        for (int w = gw; w < H; w += NWARP) {
            const float4* Wr = comb_W4 + (size_t)w * CAT4;
            float acc = 0.f;
#pragma unroll 4
            for (int k = 0; k < 19; ++k) {
                int idx = k * 32 + lane;
                if (idx < CAT4) {
                    const float4* xp = (idx < E4) ? (embrow4 + idx) : (aa4 + (idx - E4));
                    float4 a = Wr[idx], b = *xp;
                    acc += a.x * b.x + a.y * b.y + a.z * b.z + a.w * b.w;
                }
            }
            acc = warp_sum(acc);
            if (lane == 0) g_x[w] = fmaxf(acc + comb_b[w], 0.f);
        }
    }
    grid_bar();  // B3

    // ---- S4: gi = W_ih @ x : 6144 rows x 2048 ----
    for (int w = gw; w < G3H; w += NWARP) {
        const float4* Wr = Wih4 + (size_t)w * H4;
        const float4* x4 = (const float4*)g_x;
        float acc = 0.f;
#pragma unroll 8
        for (int k = 0; k < 16; ++k) {
            int idx = k * 32 + lane;
            float4 a = Wr[idx], b = x4[idx];
            acc += a.x * b.x + a.y * b.y + a.z * b.z + a.w * b.w;
        }
        acc = warp_sum(acc);
        if (lane == 0) g_gi[w] = acc + b_ih[w];
    }
    grid_bar();  // B4

    // ---- S5: GRU gates -> h_new ----
    if (gt < H) {
        float i_r = g_gi[gt],    i_z = g_gi[H + gt],    i_n = g_gi[2 * H + gt];
        float h_r = g_gh[gt],    h_z = g_gh[H + gt],    h_n = g_gh[2 * H + gt];
        float r = 1.f / (1.f + expf(-(i_r + h_r)));
        float z = 1.f / (1.f + expf(-(i_z + h_z)));
        float n = tanhf(i_n + r * h_n);
        float h = (1.f - z) * n + z * hidden[gt];
        g_hnew[gt] = h;
        out_h[gt]  = h;
    }
    grid_bar();  // B5

    // ---- S6: output GEMV 50000 x 2048 with fused online log-sum-exp ----
    {
        const float4* x4 = (const float4*)g_hnew;
        float m = -INFINITY, s = 0.f;
        for (int r = gw; r < V; r += NWARP) {
            const float4* Wr = outW4 + (size_t)r * H4;
            float acc = 0.f;
#pragma unroll 8
            for (int k = 0; k < 16; ++k) {
                int idx = k * 32 + lane;
                float4 a = Wr[idx], b = x4[idx];
                acc += a.x * b.x + a.y * b.y + a.z * b.z + a.w * b.w;
            }
            acc = warp_sum(acc);
            if (lane == 0) {
                float v = acc + out_b[r];
                g_logits[r] = v;
                float mn = fmaxf(m, v);
                s = s * expf(m - mn) + expf(v - mn);
                m = mn;
            }
        }
        if (lane == 0) { sA[wid] = m; sB[wid] = s; }
        __syncthreads();
        if (tid == 0) {
            float M = sA[0], S = sB[0];
#pragma unroll
            for (int i = 1; i < 8; ++i) {
                float m2 = sA[i], s2 = sB[i];
                float MM = fmaxf(M, m2);
                S = S * expf(M - MM) + s2 * expf(m2 - MM);
                M = MM;
            }
            g_pm[blockIdx.x] = M;
            g_ps[blockIdx.x] = S;
        }
    }
    grid_bar();  // B6

    // ---- S7: every block reduces NB (m,s) partials, finalizes its slice ----
    {
        float m = -INFINITY, s = 0.f;
        for (int i = tid; i < NB; i += NT) {
            float m2 = g_pm[i], s2 = g_ps[i];
            float M = fmaxf(m, m2);
            s = s * expf(m - M) + s2 * expf(m2 - M);
            m = M;
        }
#pragma unroll
        for (int o = 16; o; o >>= 1) {
            float m2 = __shfl_xor_sync(0xffffffffu, m, o);
            float s2 = __shfl_xor_sync(0xffffffffu, s, o);
            float M = fmaxf(m, m2);
            s = s * expf(m - M) + s2 * expf(m2 - M);
            m = M;
        }
        if (lane == 0) { sA[wid] = m; sB[wid] = s; }
        __syncthreads();
        if (tid == 0) {
            float M = sA[0], S = sB[0];
#pragma unroll
            for (int i = 1; i < 8; ++i) {
                float m2 = sA[i], s2 = sB[i];
                float MM = fmaxf(M, m2);
                S = S * expf(M - MM) + s2 * expf(m2 - MM);
                M = MM;
            }
            s_bcast = M + logf(S);
        }
        __syncthreads();
        float lse = s_bcast;
        if (gt < V) out_logp[gt] = g_logits[gt] - lse;   // NB*NT = 151552 > V
    }
}

// ---------------- launcher: ONE graph node ----------------
extern "C" void kernel_launch(void* const* d_in, const int* in_sizes, int n_in,
                              void* d_out, int out_size) {
    const int*   input  = (const int*)  d_in[0];
    const float* hidden = (const float*)d_in[1];
    const float* enc    = (const float*)d_in[2];
    const float* emb    = (const float*)d_in[3];
    const float* attn_W = (const float*)d_in[4];
    const float* attn_b = (const float*)d_in[5];
    const float* comb_W = (const float*)d_in[6];
    const float* comb_b = (const float*)d_in[7];
    const float* W_ih   = (const float*)d_in[8];
    const float* W_hh   = (const float*)d_in[9];
    const float* b_ih   = (const float*)d_in[10];
    const float* b_hh   = (const float*)d_in[11];
    const float* out_W  = (const float*)d_in[12];
    const float* out_b  = (const float*)d_in[13];

    float* out = (float*)d_out;
    float* out_logp = out;           // [V]
    float* out_h    = out + V;       // [H]
    float* out_attn = out + V + H;   // [L]

    fused_decoder<<<NB, NT>>>(input, hidden, enc, emb,
                              (const float4*)attn_W, attn_b,
                              (const float4*)comb_W, comb_b,
                              (const float4*)W_ih, (const float4*)W_hh,
                              b_ih, b_hh,
                              (const float4*)out_W, out_b,
                              out_logp, out_h, out_attn);
}